// round 12
// baseline (speedup 1.0000x reference)
#include <cuda_runtime.h>
#include <cuda_fp16.h>

#define N_NODES 50000
#define N_EDGES 1600000
#define F_IN    256
#define D       64
#define L       4
#define EPSV    1e-5f
#define ND      (N_NODES * D)
#define SCAN_B  49          // ceil(50000/1024)
#define XST     68          // smem row stride (16B-aligned for LDS.128)

typedef unsigned long long ull;

#define FFMA2(d, a, b, c) \
    asm("fma.rn.f32x2 %0, %1, %2, %3;" : "=l"(d) : "l"(a), "l"(b), "l"(c))
#define UNPACK2(lo, hi, v) \
    asm("mov.b64 {%0, %1}, %2;" : "=f"(lo), "=f"(hi) : "l"(v))

// ---------------- scratch (device globals) ----------------
__device__ float  g_W0p[F_IN * D];
__device__ float  g_c0[D];
__device__ __half g_xwh[ND];              // fp16 xw — consumed only by agg gather
__device__ float  g_sarr[N_NODES];
__device__ float  g_tarr[N_NODES];
__device__ float  g_outraw[L * (size_t)ND];   // per-layer GAT outputs (pre-GraphNorm)
__device__ int    g_deg[N_NODES];
__device__ int    g_offs[N_NODES + 1];
__device__ int    g_pos[N_NODES];
__device__ int    g_ssrc[N_EDGES];
__device__ int    g_bsum[SCAN_B];
__device__ float  g_sumf[L][D];
__device__ float  g_sqf[L][D];
__device__ int    g_smaxi[L];

// ---------------- prep: BN fold + c0 + zero ----------------
__global__ void k_prepzero(const float* __restrict__ W0, const float* __restrict__ bnw,
                           const float* __restrict__ bnb, const float* __restrict__ bnm,
                           const float* __restrict__ bnv) {
    int i = blockIdx.x * blockDim.x + threadIdx.x;
    if (i < F_IN * D) {
        int f = i / D;
        float g = bnw[f] * rsqrtf(bnv[f] + EPSV);
        g_W0p[i] = g * W0[i];
    }
    if (i < N_NODES) g_deg[i] = 0;
    if (i < L * D) {
        ((float*)g_sumf)[i] = 0.f;
        ((float*)g_sqf)[i] = 0.f;
    }
    if (i < L) g_smaxi[i] = 0;
    if (blockIdx.x == 0 && threadIdx.x < D) {
        int d = threadIdx.x;
        float acc = 0.f;
#pragma unroll 4
        for (int f = 0; f < F_IN; ++f) {
            float g = bnw[f] * rsqrtf(bnv[f] + EPSV);
            acc += (bnb[f] - bnm[f] * g) * W0[f * D + d];
        }
        g_c0[d] = acc;
    }
}

// ---------------- CSR build (by dst) ----------------
__global__ void k_count(const int* __restrict__ ei) {
    int i = blockIdx.x * blockDim.x + threadIdx.x;
    if (i * 4 < N_EDGES) {
        int4 d4 = ((const int4*)(ei + N_EDGES))[i];
        atomicAdd(&g_deg[d4.x], 1);
        atomicAdd(&g_deg[d4.y], 1);
        atomicAdd(&g_deg[d4.z], 1);
        atomicAdd(&g_deg[d4.w], 1);
    }
}

__global__ void __launch_bounds__(256) k_bsum() {
    __shared__ int wsm[8];
    int b = blockIdx.x, t = threadIdx.x;
    int base = b * 1024 + t * 4;
    int s = 0;
    if (base < N_NODES) {
        int4 d = *(const int4*)&g_deg[base];
        s = d.x + d.y + d.z + d.w;
    }
#pragma unroll
    for (int o = 16; o; o >>= 1) s += __shfl_xor_sync(0xffffffffu, s, o);
    if ((t & 31) == 0) wsm[t >> 5] = s;
    __syncthreads();
    if (t == 0) {
        int tot = 0;
#pragma unroll
        for (int w = 0; w < 8; ++w) tot += wsm[w];
        g_bsum[b] = tot;
    }
}

// local scan + write offsets; cross-block prefix computed in-block (bscan folded in)
__global__ void __launch_bounds__(256) k_offs() {
    __shared__ int wsm[8];
    __shared__ int s_pre;
    int b = blockIdx.x, t = threadIdx.x;
    int lane = t & 31, w = t >> 5;

    // warp 0: parallel sum of g_bsum[i] for i < b
    if (t < 32) {
        int v = 0;
        if (t < b) v += g_bsum[t];
        if (t + 32 < b) v += g_bsum[t + 32];
#pragma unroll
        for (int o = 16; o; o >>= 1) v += __shfl_xor_sync(0xffffffffu, v, o);
        if (t == 0) s_pre = v;
    }

    int base = b * 1024 + t * 4;
    int4 d = make_int4(0, 0, 0, 0);
    if (base < N_NODES) d = *(const int4*)&g_deg[base];
    int s = d.x + d.y + d.z + d.w;
    int x = s;
#pragma unroll
    for (int o = 1; o < 32; o <<= 1) {
        int u = __shfl_up_sync(0xffffffffu, x, o);
        if (lane >= o) x += u;
    }
    if (lane == 31) wsm[w] = x;
    __syncthreads();
    int add = 0;
#pragma unroll
    for (int i = 0; i < 8; ++i) add += (i < w) ? wsm[i] : 0;
    int run = (x - s) + add + s_pre;
    if (base < N_NODES) {
        int4 o4 = make_int4(run, run + d.x, run + d.x + d.y, run + d.x + d.y + d.z);
        *(int4*)&g_offs[base] = o4;
        *(int4*)&g_pos[base]  = o4;
    }
    if (b == 0 && t == 0) g_offs[N_NODES] = N_EDGES;
}

__global__ void k_scatter(const int* __restrict__ ei) {
    int i = blockIdx.x * blockDim.x + threadIdx.x;
    if (i * 4 < N_EDGES) {
        int4 s4 = ((const int4*)ei)[i];
        int4 d4 = ((const int4*)(ei + N_EDGES))[i];
        g_ssrc[atomicAdd(&g_pos[d4.x], 1)] = s4.x;
        g_ssrc[atomicAdd(&g_pos[d4.y], 1)] = s4.y;
        g_ssrc[atomicAdd(&g_pos[d4.z], 1)] = s4.z;
        g_ssrc[atomicAdd(&g_pos[d4.w], 1)] = s4.w;
    }
}

// ---------------- GEMM (256 thr, 8 rows/warp, FFMA2 + LDS.128) -------------------
__global__ void __launch_bounds__(256) k_gemm(
    const float* __restrict__ Xext, const float* __restrict__ W, int K,
    const float* __restrict__ asrc, const float* __restrict__ adst,
    int layer, const float* __restrict__ gnw, const float* __restrict__ gnb,
    const float* __restrict__ gns)
{
    __shared__ __align__(16) float Xs[64 * XST];
    __shared__ __align__(16) float Wt[64 * XST];
    __shared__ float sA[D], sB[D];

    int tid = threadIdx.x;
    int warp = tid >> 5, lane = tid & 31;
    int row0b = blockIdx.x * 64;

    if (layer > 0 && tid < D) {
        int lm1 = layer - 1;
        float mean = g_sumf[lm1][tid] * (1.f / N_NODES);
        float ex2  = g_sqf[lm1][tid] * (1.f / N_NODES);
        float ms = gns[tid];
        float var = ex2 - 2.f * ms * mean * mean + ms * ms * mean * mean;
        float a = gnw[tid] * rsqrtf(var + EPSV);
        sA[tid] = a;
        sB[tid] = gnb[tid] - a * ms * mean;
    }
    __syncthreads();

    ull acc0[8], acc1[8];
#pragma unroll
    for (int r = 0; r < 8; ++r) { acc0[r] = 0ULL; acc1[r] = 0ULL; }

    const float* Xprev = g_outraw + (size_t)(layer - 1) * ND;

    for (int kc = 0; kc < K; kc += 64) {
        for (int i = tid; i < 4096; i += 256) {
            int k = i >> 6, c = i & 63;
            Wt[c * XST + k] = W[(kc + k) * 64 + c];
        }
        if (layer == 0) {
            for (int i = tid; i < 1024; i += 256) {
                int r = i >> 4, k4 = (i & 15) * 4;
                int row = row0b + r;
                int re = row < N_NODES ? row : N_NODES - 1;
                float4 v = *(const float4*)&Xext[(size_t)re * F_IN + kc + k4];
                *(float4*)&Xs[r * XST + k4] = v;
            }
        } else {
            for (int i = tid; i < 1024; i += 256) {
                int r = i >> 4, k4 = (i & 15) * 4;
                int row = row0b + r;
                int re = row < N_NODES ? row : N_NODES - 1;
                float4 v = *(const float4*)&Xprev[(size_t)re * 64 + kc + k4];
                float4 y;
                y.x = sA[k4 + 0] * v.x + sB[k4 + 0]; y.x = y.x > 0.f ? y.x : 0.01f * y.x;
                y.y = sA[k4 + 1] * v.y + sB[k4 + 1]; y.y = y.y > 0.f ? y.y : 0.01f * y.y;
                y.z = sA[k4 + 2] * v.z + sB[k4 + 2]; y.z = y.z > 0.f ? y.z : 0.01f * y.z;
                y.w = sA[k4 + 3] * v.w + sB[k4 + 3]; y.w = y.w > 0.f ? y.w : 0.01f * y.w;
                *(float4*)&Xs[r * XST + k4] = y;
            }
        }
        __syncthreads();

        int c0 = lane, c1 = lane + 32;
#pragma unroll 4
        for (int jq = 0; jq < 16; ++jq) {
            ulonglong2 w0 = *(const ulonglong2*)&Wt[c0 * XST + 4 * jq];
            ulonglong2 w1 = *(const ulonglong2*)&Wt[c1 * XST + 4 * jq];
#pragma unroll
            for (int r = 0; r < 8; ++r) {
                ulonglong2 x = *(const ulonglong2*)&Xs[(warp * 8 + r) * XST + 4 * jq];
                FFMA2(acc0[r], x.x, w0.x, acc0[r]);
                FFMA2(acc0[r], x.y, w0.y, acc0[r]);
                FFMA2(acc1[r], x.x, w1.x, acc1[r]);
                FFMA2(acc1[r], x.y, w1.y, acc1[r]);
            }
        }
        __syncthreads();
    }

    int c0 = lane, c1 = lane + 32;
    float cc0 = 0.f, cc1 = 0.f;
    if (layer == 0) { cc0 = g_c0[c0]; cc1 = g_c0[c1]; }
    float a0 = asrc[c0], a1 = asrc[c1];
    float b0 = adst[c0], b1 = adst[c1];
    float maxs = 0.f;

#pragma unroll
    for (int r = 0; r < 8; ++r) {
        int row = row0b + warp * 8 + r;
        float lo, hi;
        UNPACK2(lo, hi, acc0[r]);
        float v0 = lo + hi + cc0;
        UNPACK2(lo, hi, acc1[r]);
        float v1 = lo + hi + cc1;
        float sp = v0 * a0 + v1 * a1;
        float tp = v0 * b0 + v1 * b1;
#pragma unroll
        for (int o = 16; o; o >>= 1) {
            sp += __shfl_xor_sync(0xffffffffu, sp, o);
            tp += __shfl_xor_sync(0xffffffffu, tp, o);
        }
        if (row < N_NODES) {
            g_xwh[(size_t)row * 64 + c0] = __float2half_rn(v0);
            g_xwh[(size_t)row * 64 + c1] = __float2half_rn(v1);
            if (lane == 0) { g_sarr[row] = sp; g_tarr[row] = tp; }
        }
        maxs = fmaxf(maxs, fabsf(sp));
    }
    if (lane == 0) atomicMax(&g_smaxi[layer], __float_as_int(maxs));
}

// ---- edge aggregation: warp per dst, 2-phase tiles, fp16 gather (R7-proven) -----
__global__ void __launch_bounds__(256) k_agg(const float* __restrict__ bias_l, int layer) {
    __shared__ int   s_si[8][64];
    __shared__ float s_e[8][64];
    __shared__ float s_st[8][64];
    __shared__ float s_sq[8][64];
    int warp = threadIdx.x >> 5, lane = threadIdx.x & 31;
    int row = blockIdx.x * 8 + warp;   // grid exact: 6250*8 = 50000

    int beg = g_offs[row], end = g_offs[row + 1];
    float td = g_tarr[row];
    float m = __int_as_float(g_smaxi[layer]) + td;
    m = m > 0.f ? m : 0.2f * m;

    float den = 0.f, ax = 0.f, ay = 0.f;
    const __half2* xwh2 = (const __half2*)g_xwh;

    for (int t0 = beg; t0 < end; t0 += 64) {
        int cnt = end - t0;
        if (cnt > 64) cnt = 64;
        // phase A: lane-parallel logits (random sarr gathers fly concurrently)
#pragma unroll
        for (int j = 0; j < 2; ++j) {
            int k = lane + j * 32;
            if (k < cnt) {
                int si = g_ssrc[t0 + k];
                float v = g_sarr[si] + td;
                v = v > 0.f ? v : 0.2f * v;
                s_si[warp][k] = si;
                s_e[warp][k] = __expf(v - m);
            }
        }
        __syncwarp();
        // phase B: serial gather+FMA (only the fp16 gather on the chain)
#pragma unroll 8
        for (int k = 0; k < cnt; ++k) {
            int si = s_si[warp][k];
            float e = s_e[warp][k];
            den += e;
            float2 w = __half22float2(xwh2[(size_t)si * 32 + lane]);
            ax = fmaf(e, w.x, ax);
            ay = fmaf(e, w.y, ay);
        }
        __syncwarp();
    }

    float inv = (end > beg) ? 1.f / den : 0.f;
    float2 b2 = *(const float2*)&bias_l[2 * lane];
    float2 o2;
    o2.x = ax * inv + b2.x;
    o2.y = ay * inv + b2.y;
    ((float2*)(g_outraw + (size_t)layer * ND))[(size_t)row * 32 + lane] = o2;

    // fused GraphNorm stats: block partials -> float atomics to 128 addresses
    s_st[warp][2 * lane]     = o2.x;
    s_st[warp][2 * lane + 1] = o2.y;
    s_sq[warp][2 * lane]     = o2.x * o2.x;
    s_sq[warp][2 * lane + 1] = o2.y * o2.y;
    __syncthreads();
    int tid = threadIdx.x;
    if (tid < 64) {
        float s = 0.f, q = 0.f;
#pragma unroll
        for (int w = 0; w < 8; ++w) { s += s_st[w][tid]; q += s_sq[w][tid]; }
        atomicAdd(&g_sumf[layer][tid], s);
        atomicAdd(&g_sqf[layer][tid], q);
    }
}

// ---------------- epilogue: apply all 4 norms + assemble (x, h, xs), 128-bit IO --
__global__ void __launch_bounds__(256) k_epilogue(
    float* __restrict__ out, const float* __restrict__ gnw,
    const float* __restrict__ gnb, const float* __restrict__ gns)
{
    __shared__ float sA[L][D], sB[L][D];
    int t = threadIdx.x;
    {   // 256 threads == L*D
        int l = t >> 6, f = t & 63;
        float mean = g_sumf[l][f] * (1.f / N_NODES);
        float ex2  = g_sqf[l][f] * (1.f / N_NODES);
        float ms = gns[l * D + f];
        float var = ex2 - 2.f * ms * mean * mean + ms * ms * mean * mean;
        float a = gnw[l * D + f] * rsqrtf(var + EPSV);
        sA[l][f] = a;
        sB[l][f] = gnb[l * D + f] - a * ms * mean;
    }
    __syncthreads();

    int i4 = blockIdx.x * 256 + t;       // group of 4 consecutive features
    if (i4 >= ND / 4) return;
    int f4 = (i4 & 15) * 4;

    float y[L][4];
#pragma unroll
    for (int l = 0; l < L; ++l) {
        float4 v = *(const float4*)&g_outraw[(size_t)l * ND + (size_t)i4 * 4];
        float vv[4] = {v.x, v.y, v.z, v.w};
#pragma unroll
        for (int j = 0; j < 4; ++j) {
            float yy = sA[l][f4 + j] * vv[j] + sB[l][f4 + j];
            y[l][j] = yy > 0.f ? yy : 0.01f * yy;
        }
    }

    float4 xo, ho;
    xo.x = y[3][0]; xo.y = y[3][1]; xo.z = y[3][2]; xo.w = y[3][3];
    ho.x = 0.5f * (((y[0][0] + y[1][0]) + y[2][0]) + y[3][0]);
    ho.y = 0.5f * (((y[0][1] + y[1][1]) + y[2][1]) + y[3][1]);
    ho.z = 0.5f * (((y[0][2] + y[1][2]) + y[2][2]) + y[3][2]);
    ho.w = 0.5f * (((y[0][3] + y[1][3]) + y[2][3]) + y[3][3]);

    ((float4*)out)[i4] = xo;
    ((float4*)(out + (size_t)ND))[i4] = ho;
    float4* xs4 = (float4*)(out + 2 * (size_t)ND);
#pragma unroll
    for (int j = 0; j < 4; ++j)
        xs4[(size_t)i4 * 4 + j] = make_float4(y[0][j], y[1][j], y[2][j], y[3][j]);
}

// ---------------- launch ----------------
extern "C" void kernel_launch(void* const* d_in, const int* in_sizes, int n_in,
                              void* d_out, int out_size) {
    const float* x    = (const float*)d_in[0];
    const int*   ei   = (const int*)  d_in[1];
    const float* bnw  = (const float*)d_in[2];
    const float* bnb  = (const float*)d_in[3];
    const float* bnm  = (const float*)d_in[4];
    const float* bnv  = (const float*)d_in[5];
    const float* W0   = (const float*)d_in[6];
    const float* Ws   = (const float*)d_in[7];
    const float* asrc = (const float*)d_in[8];
    const float* adst = (const float*)d_in[9];
    const float* bias = (const float*)d_in[10];
    const float* gnw  = (const float*)d_in[11];
    const float* gnb  = (const float*)d_in[12];
    const float* gns  = (const float*)d_in[13];
    float* out = (float*)d_out;

    static float* w0p_addr = nullptr;
    static cudaStream_t s2 = nullptr;
    static cudaEvent_t evA = nullptr, evB = nullptr;
    if (!w0p_addr) {
        cudaGetSymbolAddress((void**)&w0p_addr, g_W0p);
        cudaStreamCreateWithFlags(&s2, cudaStreamNonBlocking);
        cudaEventCreateWithFlags(&evA, cudaEventDisableTiming);
        cudaEventCreateWithFlags(&evB, cudaEventDisableTiming);
    }

    // prep on default stream; fork CSR build onto s2; GEMM0 runs concurrently.
    k_prepzero<<<(N_NODES + 255) / 256, 256>>>(W0, bnw, bnb, bnm, bnv);
    cudaEventRecord(evA, 0);
    cudaStreamWaitEvent(s2, evA, 0);
    k_count<<<(N_EDGES / 4 + 255) / 256, 256, 0, s2>>>(ei);
    k_bsum<<<SCAN_B, 256, 0, s2>>>();
    k_gemm<<<(N_NODES + 63) / 64, 256>>>(x, w0p_addr, F_IN, asrc, adst, 0,
                                         gnw, gnb, gns);
    k_offs<<<SCAN_B, 256, 0, s2>>>();
    k_scatter<<<(N_EDGES / 4 + 255) / 256, 256, 0, s2>>>(ei);
    cudaEventRecord(evB, s2);
    cudaStreamWaitEvent(0, evB, 0);   // join before agg needs the CSR

    for (int l = 0; l < L; ++l) {
        if (l > 0) {
            const float* W = Ws + (size_t)(l - 1) * D * D;
            k_gemm<<<(N_NODES + 63) / 64, 256>>>(
                nullptr, W, D, asrc + l * D, adst + l * D, l,
                gnw + (l - 1) * D, gnb + (l - 1) * D, gns + (l - 1) * D);
        }
        k_agg<<<N_NODES / 8, 256>>>(bias + l * D, l);
    }
    k_epilogue<<<(ND / 4 + 255) / 256, 256>>>(out, gnw, gnb, gns);
}

// round 13
// speedup vs baseline: 1.0039x; 1.0039x over previous
#include <cuda_runtime.h>
#include <cuda_fp16.h>

#define N_NODES 50000
#define N_EDGES 1600000
#define F_IN    256
#define D       64
#define L       4
#define EPSV    1e-5f
#define ND      (N_NODES * D)
#define SCAN_B  49          // ceil(50000/1024)
#define XST     68          // smem row stride (16B-aligned for LDS.128)

typedef unsigned long long ull;

#define FFMA2(d, a, b, c) \
    asm("fma.rn.f32x2 %0, %1, %2, %3;" : "=l"(d) : "l"(a), "l"(b), "l"(c))
#define UNPACK2(lo, hi, v) \
    asm("mov.b64 {%0, %1}, %2;" : "=f"(lo), "=f"(hi) : "l"(v))

// ---------------- scratch (device globals) ----------------
__device__ float  g_W0p[F_IN * D];
__device__ float  g_c0[D];
__device__ __half g_xwh[ND];          // fp16 xw — consumed only by agg gather
__device__ float  g_sarr[N_NODES];
__device__ float  g_tarr[N_NODES];
__device__ float  g_outraw[ND];
__device__ float  g_xs[3 * (size_t)ND];
__device__ int    g_deg[N_NODES];
__device__ int    g_offs[N_NODES + 1];
__device__ int    g_pos[N_NODES];
__device__ int    g_ssrc[N_EDGES];
__device__ int    g_bsum[SCAN_B];
__device__ int    g_bpre[SCAN_B];
__device__ float  g_sumf[L][D];
__device__ float  g_sqf[L][D];
__device__ int    g_smaxi[L];

// ---------------- prep: BN fold + c0 + zero ----------------
__global__ void k_prepzero(const float* __restrict__ W0, const float* __restrict__ bnw,
                           const float* __restrict__ bnb, const float* __restrict__ bnm,
                           const float* __restrict__ bnv) {
    int i = blockIdx.x * blockDim.x + threadIdx.x;
    if (i < F_IN * D) {
        int f = i / D;
        float g = bnw[f] * rsqrtf(bnv[f] + EPSV);
        g_W0p[i] = g * W0[i];
    }
    if (i < N_NODES) g_deg[i] = 0;
    if (i < L * D) {
        ((float*)g_sumf)[i] = 0.f;
        ((float*)g_sqf)[i] = 0.f;
    }
    if (i < L) g_smaxi[i] = 0;
    if (blockIdx.x == 0 && threadIdx.x < D) {
        int d = threadIdx.x;
        float acc = 0.f;
#pragma unroll 4
        for (int f = 0; f < F_IN; ++f) {
            float g = bnw[f] * rsqrtf(bnv[f] + EPSV);
            acc += (bnb[f] - bnm[f] * g) * W0[f * D + d];
        }
        g_c0[d] = acc;
    }
}

// ---------------- CSR build (by dst) ----------------
__global__ void k_count(const int* __restrict__ ei) {
    int i = blockIdx.x * blockDim.x + threadIdx.x;
    if (i * 4 < N_EDGES) {
        int4 d4 = ((const int4*)(ei + N_EDGES))[i];
        atomicAdd(&g_deg[d4.x], 1);
        atomicAdd(&g_deg[d4.y], 1);
        atomicAdd(&g_deg[d4.z], 1);
        atomicAdd(&g_deg[d4.w], 1);
    }
}

__global__ void __launch_bounds__(256) k_bsum() {
    __shared__ int wsm[8];
    int b = blockIdx.x, t = threadIdx.x;
    int base = b * 1024 + t * 4;
    int s = 0;
    if (base < N_NODES) {
        int4 d = *(const int4*)&g_deg[base];
        s = d.x + d.y + d.z + d.w;
    }
#pragma unroll
    for (int o = 16; o; o >>= 1) s += __shfl_xor_sync(0xffffffffu, s, o);
    if ((t & 31) == 0) wsm[t >> 5] = s;
    __syncthreads();
    if (t == 0) {
        int tot = 0;
#pragma unroll
        for (int w = 0; w < 8; ++w) tot += wsm[w];
        g_bsum[b] = tot;
    }
}

__global__ void k_bscan() {
    __shared__ int sm[64];
    int t = threadIdx.x;
    int v = (t < SCAN_B) ? g_bsum[t] : 0;
    sm[t] = v;
    __syncthreads();
#pragma unroll
    for (int o = 1; o < 64; o <<= 1) {
        int u = (t >= o) ? sm[t - o] : 0;
        __syncthreads();
        sm[t] += u;
        __syncthreads();
    }
    if (t < SCAN_B) g_bpre[t] = sm[t] - v;   // exclusive
}

__global__ void __launch_bounds__(256) k_offs() {
    __shared__ int wsm[8];
    int b = blockIdx.x, t = threadIdx.x;
    int lane = t & 31, w = t >> 5;
    int base = b * 1024 + t * 4;
    int4 d = make_int4(0, 0, 0, 0);
    if (base < N_NODES) d = *(const int4*)&g_deg[base];
    int s = d.x + d.y + d.z + d.w;
    int x = s;
#pragma unroll
    for (int o = 1; o < 32; o <<= 1) {
        int u = __shfl_up_sync(0xffffffffu, x, o);
        if (lane >= o) x += u;
    }
    if (lane == 31) wsm[w] = x;
    __syncthreads();
    int add = 0;
#pragma unroll
    for (int i = 0; i < 8; ++i) add += (i < w) ? wsm[i] : 0;
    int run = (x - s) + add + g_bpre[b];
    if (base < N_NODES) {
        int4 o4 = make_int4(run, run + d.x, run + d.x + d.y, run + d.x + d.y + d.z);
        *(int4*)&g_offs[base] = o4;
        *(int4*)&g_pos[base]  = o4;
    }
    if (b == 0 && t == 0) g_offs[N_NODES] = N_EDGES;
}

__global__ void k_scatter(const int* __restrict__ ei) {
    int i = blockIdx.x * blockDim.x + threadIdx.x;
    if (i * 4 < N_EDGES) {
        int4 s4 = ((const int4*)ei)[i];
        int4 d4 = ((const int4*)(ei + N_EDGES))[i];
        g_ssrc[atomicAdd(&g_pos[d4.x], 1)] = s4.x;
        g_ssrc[atomicAdd(&g_pos[d4.y], 1)] = s4.y;
        g_ssrc[atomicAdd(&g_pos[d4.z], 1)] = s4.z;
        g_ssrc[atomicAdd(&g_pos[d4.w], 1)] = s4.w;
    }
}

// ---------------- GEMM (256 thr, 8 rows/warp, FFMA2 + LDS.128) -------------------
__global__ void __launch_bounds__(256) k_gemm(
    const float* __restrict__ Xext, const float* __restrict__ W, int K,
    const float* __restrict__ asrc, const float* __restrict__ adst,
    int layer, const float* __restrict__ gnw, const float* __restrict__ gnb,
    const float* __restrict__ gns)
{
    __shared__ __align__(16) float Xs[64 * XST];
    __shared__ __align__(16) float Wt[64 * XST];
    __shared__ float sA[D], sB[D];

    int tid = threadIdx.x;
    int warp = tid >> 5, lane = tid & 31;
    int row0b = blockIdx.x * 64;

    if (layer > 0 && tid < D) {
        int lm1 = layer - 1;
        float mean = g_sumf[lm1][tid] * (1.f / N_NODES);
        float ex2  = g_sqf[lm1][tid] * (1.f / N_NODES);
        float ms = gns[tid];
        float var = ex2 - 2.f * ms * mean * mean + ms * ms * mean * mean;
        float a = gnw[tid] * rsqrtf(var + EPSV);
        sA[tid] = a;
        sB[tid] = gnb[tid] - a * ms * mean;
    }
    __syncthreads();

    ull acc0[8], acc1[8];
#pragma unroll
    for (int r = 0; r < 8; ++r) { acc0[r] = 0ULL; acc1[r] = 0ULL; }

    for (int kc = 0; kc < K; kc += 64) {
        for (int i = tid; i < 4096; i += 256) {
            int k = i >> 6, c = i & 63;
            Wt[c * XST + k] = W[(kc + k) * 64 + c];
        }
        if (layer == 0) {
            for (int i = tid; i < 1024; i += 256) {
                int r = i >> 4, k4 = (i & 15) * 4;
                int row = row0b + r;
                int re = row < N_NODES ? row : N_NODES - 1;
                float4 v = *(const float4*)&Xext[(size_t)re * F_IN + kc + k4];
                *(float4*)&Xs[r * XST + k4] = v;
            }
        } else {
            for (int i = tid; i < 1024; i += 256) {
                int r = i >> 4, k4 = (i & 15) * 4;
                int row = row0b + r;
                int re = row < N_NODES ? row : N_NODES - 1;
                float4 v = *(const float4*)&g_outraw[(size_t)re * 64 + kc + k4];
                float4 y;
                y.x = sA[k4 + 0] * v.x + sB[k4 + 0]; y.x = y.x > 0.f ? y.x : 0.01f * y.x;
                y.y = sA[k4 + 1] * v.y + sB[k4 + 1]; y.y = y.y > 0.f ? y.y : 0.01f * y.y;
                y.z = sA[k4 + 2] * v.z + sB[k4 + 2]; y.z = y.z > 0.f ? y.z : 0.01f * y.z;
                y.w = sA[k4 + 3] * v.w + sB[k4 + 3]; y.w = y.w > 0.f ? y.w : 0.01f * y.w;
                *(float4*)&Xs[r * XST + k4] = y;
                if (row < N_NODES)
                    *(float4*)&g_xs[(size_t)(layer - 1) * ND + (size_t)row * 64 + kc + k4] = y;
            }
        }
        __syncthreads();

        int c0 = lane, c1 = lane + 32;
#pragma unroll 4
        for (int jq = 0; jq < 16; ++jq) {
            ulonglong2 w0 = *(const ulonglong2*)&Wt[c0 * XST + 4 * jq];
            ulonglong2 w1 = *(const ulonglong2*)&Wt[c1 * XST + 4 * jq];
#pragma unroll
            for (int r = 0; r < 8; ++r) {
                ulonglong2 x = *(const ulonglong2*)&Xs[(warp * 8 + r) * XST + 4 * jq];
                FFMA2(acc0[r], x.x, w0.x, acc0[r]);
                FFMA2(acc0[r], x.y, w0.y, acc0[r]);
                FFMA2(acc1[r], x.x, w1.x, acc1[r]);
                FFMA2(acc1[r], x.y, w1.y, acc1[r]);
            }
        }
        __syncthreads();
    }

    int c0 = lane, c1 = lane + 32;
    float cc0 = 0.f, cc1 = 0.f;
    if (layer == 0) { cc0 = g_c0[c0]; cc1 = g_c0[c1]; }
    float a0 = asrc[c0], a1 = asrc[c1];
    float b0 = adst[c0], b1 = adst[c1];
    float maxs = 0.f;

#pragma unroll
    for (int r = 0; r < 8; ++r) {
        int row = row0b + warp * 8 + r;
        float lo, hi;
        UNPACK2(lo, hi, acc0[r]);
        float v0 = lo + hi + cc0;
        UNPACK2(lo, hi, acc1[r]);
        float v1 = lo + hi + cc1;
        float sp = v0 * a0 + v1 * a1;
        float tp = v0 * b0 + v1 * b1;
#pragma unroll
        for (int o = 16; o; o >>= 1) {
            sp += __shfl_xor_sync(0xffffffffu, sp, o);
            tp += __shfl_xor_sync(0xffffffffu, tp, o);
        }
        if (row < N_NODES) {
            g_xwh[(size_t)row * 64 + c0] = __float2half_rn(v0);
            g_xwh[(size_t)row * 64 + c1] = __float2half_rn(v1);
            if (lane == 0) { g_sarr[row] = sp; g_tarr[row] = tp; }
        }
        maxs = fmaxf(maxs, fabsf(sp));
    }
    if (lane == 0) atomicMax(&g_smaxi[layer], __float_as_int(maxs));
}

// ---- edge aggregation: warp per dst, 2-phase tiles, fp16 gather (R7-proven) -----
__global__ void __launch_bounds__(256) k_agg(const float* __restrict__ bias_l, int layer) {
    __shared__ int   s_si[8][64];
    __shared__ float s_e[8][64];
    __shared__ float s_st[8][64];
    __shared__ float s_sq[8][64];
    int warp = threadIdx.x >> 5, lane = threadIdx.x & 31;
    int row = blockIdx.x * 8 + warp;   // grid exact: 6250*8 = 50000

    int beg = g_offs[row], end = g_offs[row + 1];
    float td = g_tarr[row];
    float m = __int_as_float(g_smaxi[layer]) + td;
    m = m > 0.f ? m : 0.2f * m;

    float den = 0.f, ax = 0.f, ay = 0.f;
    const __half2* xwh2 = (const __half2*)g_xwh;

    for (int t0 = beg; t0 < end; t0 += 64) {
        int cnt = end - t0;
        if (cnt > 64) cnt = 64;
        // phase A: lane-parallel logits (random sarr gathers fly concurrently)
#pragma unroll
        for (int j = 0; j < 2; ++j) {
            int k = lane + j * 32;
            if (k < cnt) {
                int si = g_ssrc[t0 + k];
                float v = g_sarr[si] + td;
                v = v > 0.f ? v : 0.2f * v;
                s_si[warp][k] = si;
                s_e[warp][k] = __expf(v - m);
            }
        }
        __syncwarp();
        // phase B: serial gather+FMA (only the fp16 gather on the chain)
#pragma unroll 8
        for (int k = 0; k < cnt; ++k) {
            int si = s_si[warp][k];
            float e = s_e[warp][k];
            den += e;
            float2 w = __half22float2(xwh2[(size_t)si * 32 + lane]);
            ax = fmaf(e, w.x, ax);
            ay = fmaf(e, w.y, ay);
        }
        __syncwarp();
    }

    float inv = (end > beg) ? 1.f / den : 0.f;
    float2 b2 = *(const float2*)&bias_l[2 * lane];
    float2 o2;
    o2.x = ax * inv + b2.x;
    o2.y = ay * inv + b2.y;
    ((float2*)g_outraw)[(size_t)row * 32 + lane] = o2;

    // fused GraphNorm stats: block partials -> float atomics to 128 addresses
    s_st[warp][2 * lane]     = o2.x;
    s_st[warp][2 * lane + 1] = o2.y;
    s_sq[warp][2 * lane]     = o2.x * o2.x;
    s_sq[warp][2 * lane + 1] = o2.y * o2.y;
    __syncthreads();
    int tid = threadIdx.x;
    if (tid < 64) {
        float s = 0.f, q = 0.f;
#pragma unroll
        for (int w = 0; w < 8; ++w) { s += s_st[w][tid]; q += s_sq[w][tid]; }
        atomicAdd(&g_sumf[layer][tid], s);
        atomicAdd(&g_sqf[layer][tid], q);
    }
}

// ---------------- epilogue: layer-3 norm + assemble (x, h, xs) ----------------
__global__ void __launch_bounds__(256) k_epilogue(
    float* __restrict__ out, const float* __restrict__ gnw,
    const float* __restrict__ gnb, const float* __restrict__ gns)
{
    __shared__ float sA[D], sB[D];
    if (threadIdx.x < D) {
        int f = threadIdx.x;
        float mean = g_sumf[3][f] * (1.f / N_NODES);
        float ex2  = g_sqf[3][f] * (1.f / N_NODES);
        float ms = gns[f];
        float var = ex2 - 2.f * ms * mean * mean + ms * ms * mean * mean;
        float a = gnw[f] * rsqrtf(var + EPSV);
        sA[f] = a;
        sB[f] = gnb[f] - a * ms * mean;
    }
    __syncthreads();

    int idx = blockIdx.x * 256 + threadIdx.x;
    if (idx >= ND) return;
    int f = idx & 63;
    float v3 = g_outraw[idx];
    float y3 = sA[f] * v3 + sB[f];
    y3 = y3 > 0.f ? y3 : 0.01f * y3;
    float v0 = g_xs[idx];
    float v1 = g_xs[(size_t)ND + idx];
    float v2 = g_xs[2 * (size_t)ND + idx];
    out[idx] = y3;
    out[(size_t)ND + idx] = 0.5f * (((v0 + v1) + v2) + y3);
    ((float4*)(out + 2 * (size_t)ND))[idx] = make_float4(v0, v1, v2, y3);
}

// ---------------- launch ----------------
extern "C" void kernel_launch(void* const* d_in, const int* in_sizes, int n_in,
                              void* d_out, int out_size) {
    const float* x    = (const float*)d_in[0];
    const int*   ei   = (const int*)  d_in[1];
    const float* bnw  = (const float*)d_in[2];
    const float* bnb  = (const float*)d_in[3];
    const float* bnm  = (const float*)d_in[4];
    const float* bnv  = (const float*)d_in[5];
    const float* W0   = (const float*)d_in[6];
    const float* Ws   = (const float*)d_in[7];
    const float* asrc = (const float*)d_in[8];
    const float* adst = (const float*)d_in[9];
    const float* bias = (const float*)d_in[10];
    const float* gnw  = (const float*)d_in[11];
    const float* gnb  = (const float*)d_in[12];
    const float* gns  = (const float*)d_in[13];
    float* out = (float*)d_out;

    static float* w0p_addr = nullptr;
    static cudaStream_t s2 = nullptr;
    static cudaEvent_t evA = nullptr, evB = nullptr;
    if (!w0p_addr) {
        cudaGetSymbolAddress((void**)&w0p_addr, g_W0p);
        cudaStreamCreateWithFlags(&s2, cudaStreamNonBlocking);
        cudaEventCreateWithFlags(&evA, cudaEventDisableTiming);
        cudaEventCreateWithFlags(&evB, cudaEventDisableTiming);
    }

    // prep on default stream; fork CSR build onto s2; GEMM0 runs concurrently.
    k_prepzero<<<(N_NODES + 255) / 256, 256>>>(W0, bnw, bnb, bnm, bnv);
    cudaEventRecord(evA, 0);
    cudaStreamWaitEvent(s2, evA, 0);
    k_count<<<(N_EDGES / 4 + 255) / 256, 256, 0, s2>>>(ei);
    k_bsum<<<SCAN_B, 256, 0, s2>>>();
    k_gemm<<<(N_NODES + 63) / 64, 256>>>(x, w0p_addr, F_IN, asrc, adst, 0,
                                         gnw, gnb, gns);
    k_bscan<<<1, 64, 0, s2>>>();
    k_offs<<<SCAN_B, 256, 0, s2>>>();
    k_scatter<<<(N_EDGES / 4 + 255) / 256, 256, 0, s2>>>(ei);
    cudaEventRecord(evB, s2);
    cudaStreamWaitEvent(0, evB, 0);   // join before agg needs the CSR

    for (int l = 0; l < L; ++l) {
        if (l > 0) {
            const float* W = Ws + (size_t)(l - 1) * D * D;
            k_gemm<<<(N_NODES + 63) / 64, 256>>>(
                nullptr, W, D, asrc + l * D, adst + l * D, l,
                gnw + (l - 1) * D, gnb + (l - 1) * D, gns + (l - 1) * D);
        }
        k_agg<<<N_NODES / 8, 256>>>(bias + l * D, l);
    }
    k_epilogue<<<(ND + 255) / 256, 256>>>(out, gnw + 3 * D, gnb + 3 * D, gns + 3 * D);
}

// round 14
// speedup vs baseline: 1.0292x; 1.0252x over previous
#include <cuda_runtime.h>
#include <cuda_fp16.h>

#define N_NODES 50000
#define N_EDGES 1600000
#define F_IN    256
#define D       64
#define L       4
#define EPSV    1e-5f
#define ND      (N_NODES * D)
#define SCAN_B  49          // ceil(50000/1024)
#define XST     68          // smem row stride (16B-aligned for LDS.128)

typedef unsigned long long ull;

#define FFMA2(d, a, b, c) \
    asm("fma.rn.f32x2 %0, %1, %2, %3;" : "=l"(d) : "l"(a), "l"(b), "l"(c))
#define UNPACK2(lo, hi, v) \
    asm("mov.b64 {%0, %1}, %2;" : "=f"(lo), "=f"(hi) : "l"(v))

// ---------------- scratch (device globals) ----------------
__device__ float  g_W0p[F_IN * D];
__device__ float  g_c0[D];
__device__ __half g_xwh[ND];          // fp16 xw — consumed only by agg gather
__device__ float  g_sarr[N_NODES];
__device__ float  g_tarr[N_NODES];
__device__ float  g_outraw[ND];
__device__ float  g_xs[3 * (size_t)ND];
__device__ int    g_deg[N_NODES];
__device__ int    g_offs[N_NODES + 1];
__device__ int    g_pos[N_NODES];
__device__ int    g_ssrc[N_EDGES];
__device__ int    g_bsum[SCAN_B];
__device__ int    g_bpre[SCAN_B];
__device__ float  g_sumf[L][D];
__device__ float  g_sqf[L][D];
__device__ int    g_smaxi[L];

// ---------------- prep: BN fold + c0 + zero ----------------
__global__ void k_prepzero(const float* __restrict__ W0, const float* __restrict__ bnw,
                           const float* __restrict__ bnb, const float* __restrict__ bnm,
                           const float* __restrict__ bnv) {
    int i = blockIdx.x * blockDim.x + threadIdx.x;
    if (i < F_IN * D) {
        int f = i / D;
        float g = bnw[f] * rsqrtf(bnv[f] + EPSV);
        g_W0p[i] = g * W0[i];
    }
    if (i < N_NODES) g_deg[i] = 0;
    if (i < L * D) {
        ((float*)g_sumf)[i] = 0.f;
        ((float*)g_sqf)[i] = 0.f;
    }
    if (i < L) g_smaxi[i] = 0;
    if (blockIdx.x == 0 && threadIdx.x < D) {
        int d = threadIdx.x;
        float acc = 0.f;
#pragma unroll 4
        for (int f = 0; f < F_IN; ++f) {
            float g = bnw[f] * rsqrtf(bnv[f] + EPSV);
            acc += (bnb[f] - bnm[f] * g) * W0[f * D + d];
        }
        g_c0[d] = acc;
    }
}

// ---------------- CSR build (by dst) ----------------
__global__ void k_count(const int* __restrict__ ei) {
    int i = blockIdx.x * blockDim.x + threadIdx.x;
    if (i * 4 < N_EDGES) {
        int4 d4 = ((const int4*)(ei + N_EDGES))[i];
        atomicAdd(&g_deg[d4.x], 1);
        atomicAdd(&g_deg[d4.y], 1);
        atomicAdd(&g_deg[d4.z], 1);
        atomicAdd(&g_deg[d4.w], 1);
    }
}

__global__ void __launch_bounds__(256) k_bsum() {
    __shared__ int wsm[8];
    int b = blockIdx.x, t = threadIdx.x;
    int base = b * 1024 + t * 4;
    int s = 0;
    if (base < N_NODES) {
        int4 d = *(const int4*)&g_deg[base];
        s = d.x + d.y + d.z + d.w;
    }
#pragma unroll
    for (int o = 16; o; o >>= 1) s += __shfl_xor_sync(0xffffffffu, s, o);
    if ((t & 31) == 0) wsm[t >> 5] = s;
    __syncthreads();
    if (t == 0) {
        int tot = 0;
#pragma unroll
        for (int w = 0; w < 8; ++w) tot += wsm[w];
        g_bsum[b] = tot;
    }
}

__global__ void k_bscan() {
    __shared__ int sm[64];
    int t = threadIdx.x;
    int v = (t < SCAN_B) ? g_bsum[t] : 0;
    sm[t] = v;
    __syncthreads();
#pragma unroll
    for (int o = 1; o < 64; o <<= 1) {
        int u = (t >= o) ? sm[t - o] : 0;
        __syncthreads();
        sm[t] += u;
        __syncthreads();
    }
    if (t < SCAN_B) g_bpre[t] = sm[t] - v;   // exclusive
}

__global__ void __launch_bounds__(256) k_offs() {
    __shared__ int wsm[8];
    int b = blockIdx.x, t = threadIdx.x;
    int lane = t & 31, w = t >> 5;
    int base = b * 1024 + t * 4;
    int4 d = make_int4(0, 0, 0, 0);
    if (base < N_NODES) d = *(const int4*)&g_deg[base];
    int s = d.x + d.y + d.z + d.w;
    int x = s;
#pragma unroll
    for (int o = 1; o < 32; o <<= 1) {
        int u = __shfl_up_sync(0xffffffffu, x, o);
        if (lane >= o) x += u;
    }
    if (lane == 31) wsm[w] = x;
    __syncthreads();
    int add = 0;
#pragma unroll
    for (int i = 0; i < 8; ++i) add += (i < w) ? wsm[i] : 0;
    int run = (x - s) + add + g_bpre[b];
    if (base < N_NODES) {
        int4 o4 = make_int4(run, run + d.x, run + d.x + d.y, run + d.x + d.y + d.z);
        *(int4*)&g_offs[base] = o4;
        *(int4*)&g_pos[base]  = o4;
    }
    if (b == 0 && t == 0) g_offs[N_NODES] = N_EDGES;
}

__global__ void k_scatter(const int* __restrict__ ei) {
    int i = blockIdx.x * blockDim.x + threadIdx.x;
    if (i * 4 < N_EDGES) {
        int4 s4 = ((const int4*)ei)[i];
        int4 d4 = ((const int4*)(ei + N_EDGES))[i];
        g_ssrc[atomicAdd(&g_pos[d4.x], 1)] = s4.x;
        g_ssrc[atomicAdd(&g_pos[d4.y], 1)] = s4.y;
        g_ssrc[atomicAdd(&g_pos[d4.z], 1)] = s4.z;
        g_ssrc[atomicAdd(&g_pos[d4.w], 1)] = s4.w;
    }
}

// ---------------- GEMM (256 thr, 8 rows/warp, FFMA2 + LDS.128) -------------------
__global__ void __launch_bounds__(256) k_gemm(
    const float* __restrict__ Xext, const float* __restrict__ W, int K,
    const float* __restrict__ asrc, const float* __restrict__ adst,
    int layer, const float* __restrict__ gnw, const float* __restrict__ gnb,
    const float* __restrict__ gns)
{
    __shared__ __align__(16) float Xs[64 * XST];
    __shared__ __align__(16) float Wt[64 * XST];
    __shared__ float sA[D], sB[D];

    int tid = threadIdx.x;
    int warp = tid >> 5, lane = tid & 31;
    int row0b = blockIdx.x * 64;

    if (layer > 0 && tid < D) {
        int lm1 = layer - 1;
        float mean = g_sumf[lm1][tid] * (1.f / N_NODES);
        float ex2  = g_sqf[lm1][tid] * (1.f / N_NODES);
        float ms = gns[tid];
        float var = ex2 - 2.f * ms * mean * mean + ms * ms * mean * mean;
        float a = gnw[tid] * rsqrtf(var + EPSV);
        sA[tid] = a;
        sB[tid] = gnb[tid] - a * ms * mean;
    }
    __syncthreads();

    ull acc0[8], acc1[8];
#pragma unroll
    for (int r = 0; r < 8; ++r) { acc0[r] = 0ULL; acc1[r] = 0ULL; }

    for (int kc = 0; kc < K; kc += 64) {
        // stage W transposed: conflict-free STS.128 per k-quad; LDGs stay coalesced
        for (int i = tid; i < 1024; i += 256) {
            int c = i & 63, kq = i >> 6;
            const float* Wp = W + (size_t)(kc + kq * 4) * 64 + c;
            float w0 = Wp[0];
            float w1 = Wp[64];
            float w2 = Wp[128];
            float w3 = Wp[192];
            *(float4*)&Wt[c * XST + kq * 4] = make_float4(w0, w1, w2, w3);
        }
        if (layer == 0) {
            for (int i = tid; i < 1024; i += 256) {
                int r = i >> 4, k4 = (i & 15) * 4;
                int row = row0b + r;
                int re = row < N_NODES ? row : N_NODES - 1;
                float4 v = *(const float4*)&Xext[(size_t)re * F_IN + kc + k4];
                *(float4*)&Xs[r * XST + k4] = v;
            }
        } else {
            for (int i = tid; i < 1024; i += 256) {
                int r = i >> 4, k4 = (i & 15) * 4;
                int row = row0b + r;
                int re = row < N_NODES ? row : N_NODES - 1;
                float4 v = *(const float4*)&g_outraw[(size_t)re * 64 + kc + k4];
                float4 y;
                y.x = sA[k4 + 0] * v.x + sB[k4 + 0]; y.x = y.x > 0.f ? y.x : 0.01f * y.x;
                y.y = sA[k4 + 1] * v.y + sB[k4 + 1]; y.y = y.y > 0.f ? y.y : 0.01f * y.y;
                y.z = sA[k4 + 2] * v.z + sB[k4 + 2]; y.z = y.z > 0.f ? y.z : 0.01f * y.z;
                y.w = sA[k4 + 3] * v.w + sB[k4 + 3]; y.w = y.w > 0.f ? y.w : 0.01f * y.w;
                *(float4*)&Xs[r * XST + k4] = y;
                if (row < N_NODES)
                    *(float4*)&g_xs[(size_t)(layer - 1) * ND + (size_t)row * 64 + kc + k4] = y;
            }
        }
        __syncthreads();

        int c0 = lane, c1 = lane + 32;
#pragma unroll 4
        for (int jq = 0; jq < 16; ++jq) {
            ulonglong2 w0 = *(const ulonglong2*)&Wt[c0 * XST + 4 * jq];
            ulonglong2 w1 = *(const ulonglong2*)&Wt[c1 * XST + 4 * jq];
#pragma unroll
            for (int r = 0; r < 8; ++r) {
                ulonglong2 x = *(const ulonglong2*)&Xs[(warp * 8 + r) * XST + 4 * jq];
                FFMA2(acc0[r], x.x, w0.x, acc0[r]);
                FFMA2(acc0[r], x.y, w0.y, acc0[r]);
                FFMA2(acc1[r], x.x, w1.x, acc1[r]);
                FFMA2(acc1[r], x.y, w1.y, acc1[r]);
            }
        }
        __syncthreads();
    }

    int c0 = lane, c1 = lane + 32;
    float cc0 = 0.f, cc1 = 0.f;
    if (layer == 0) { cc0 = g_c0[c0]; cc1 = g_c0[c1]; }
    float a0 = asrc[c0], a1 = asrc[c1];
    float b0 = adst[c0], b1 = adst[c1];
    float maxs = 0.f;

#pragma unroll
    for (int r = 0; r < 8; ++r) {
        int row = row0b + warp * 8 + r;
        float lo, hi;
        UNPACK2(lo, hi, acc0[r]);
        float v0 = lo + hi + cc0;
        UNPACK2(lo, hi, acc1[r]);
        float v1 = lo + hi + cc1;
        float sp = v0 * a0 + v1 * a1;
        float tp = v0 * b0 + v1 * b1;
#pragma unroll
        for (int o = 16; o; o >>= 1) {
            sp += __shfl_xor_sync(0xffffffffu, sp, o);
            tp += __shfl_xor_sync(0xffffffffu, tp, o);
        }
        if (row < N_NODES) {
            g_xwh[(size_t)row * 64 + c0] = __float2half_rn(v0);
            g_xwh[(size_t)row * 64 + c1] = __float2half_rn(v1);
            if (lane == 0) { g_sarr[row] = sp; g_tarr[row] = tp; }
        }
        maxs = fmaxf(maxs, fabsf(sp));
    }
    if (lane == 0) atomicMax(&g_smaxi[layer], __float_as_int(maxs));
}

// ---- edge aggregation: warp per dst, 2-phase tiles, fp16 gather (R7-proven) -----
__global__ void __launch_bounds__(256) k_agg(const float* __restrict__ bias_l, int layer) {
    __shared__ int   s_si[8][64];
    __shared__ float s_e[8][64];
    __shared__ float s_st[8][64];
    __shared__ float s_sq[8][64];
    int warp = threadIdx.x >> 5, lane = threadIdx.x & 31;
    int row = blockIdx.x * 8 + warp;   // grid exact: 6250*8 = 50000

    int beg = g_offs[row], end = g_offs[row + 1];
    float td = g_tarr[row];
    float m = __int_as_float(g_smaxi[layer]) + td;
    m = m > 0.f ? m : 0.2f * m;

    float den = 0.f, ax = 0.f, ay = 0.f;
    const __half2* xwh2 = (const __half2*)g_xwh;

    for (int t0 = beg; t0 < end; t0 += 64) {
        int cnt = end - t0;
        if (cnt > 64) cnt = 64;
        // phase A: lane-parallel logits (random sarr gathers fly concurrently)
#pragma unroll
        for (int j = 0; j < 2; ++j) {
            int k = lane + j * 32;
            if (k < cnt) {
                int si = g_ssrc[t0 + k];
                float v = g_sarr[si] + td;
                v = v > 0.f ? v : 0.2f * v;
                s_si[warp][k] = si;
                s_e[warp][k] = __expf(v - m);
            }
        }
        __syncwarp();
        // phase B: serial gather+FMA (only the fp16 gather on the chain)
#pragma unroll 8
        for (int k = 0; k < cnt; ++k) {
            int si = s_si[warp][k];
            float e = s_e[warp][k];
            den += e;
            float2 w = __half22float2(xwh2[(size_t)si * 32 + lane]);
            ax = fmaf(e, w.x, ax);
            ay = fmaf(e, w.y, ay);
        }
        __syncwarp();
    }

    float inv = (end > beg) ? 1.f / den : 0.f;
    float2 b2 = *(const float2*)&bias_l[2 * lane];
    float2 o2;
    o2.x = ax * inv + b2.x;
    o2.y = ay * inv + b2.y;
    ((float2*)g_outraw)[(size_t)row * 32 + lane] = o2;

    // fused GraphNorm stats: block partials -> float atomics to 128 addresses
    s_st[warp][2 * lane]     = o2.x;
    s_st[warp][2 * lane + 1] = o2.y;
    s_sq[warp][2 * lane]     = o2.x * o2.x;
    s_sq[warp][2 * lane + 1] = o2.y * o2.y;
    __syncthreads();
    int tid = threadIdx.x;
    if (tid < 64) {
        float s = 0.f, q = 0.f;
#pragma unroll
        for (int w = 0; w < 8; ++w) { s += s_st[w][tid]; q += s_sq[w][tid]; }
        atomicAdd(&g_sumf[layer][tid], s);
        atomicAdd(&g_sqf[layer][tid], q);
    }
}

// ---------------- epilogue: layer-3 norm + assemble (x, h, xs) ----------------
__global__ void __launch_bounds__(256) k_epilogue(
    float* __restrict__ out, const float* __restrict__ gnw,
    const float* __restrict__ gnb, const float* __restrict__ gns)
{
    __shared__ float sA[D], sB[D];
    if (threadIdx.x < D) {
        int f = threadIdx.x;
        float mean = g_sumf[3][f] * (1.f / N_NODES);
        float ex2  = g_sqf[3][f] * (1.f / N_NODES);
        float ms = gns[f];
        float var = ex2 - 2.f * ms * mean * mean + ms * ms * mean * mean;
        float a = gnw[f] * rsqrtf(var + EPSV);
        sA[f] = a;
        sB[f] = gnb[f] - a * ms * mean;
    }
    __syncthreads();

    int idx = blockIdx.x * 256 + threadIdx.x;
    if (idx >= ND) return;
    int f = idx & 63;
    float v3 = g_outraw[idx];
    float y3 = sA[f] * v3 + sB[f];
    y3 = y3 > 0.f ? y3 : 0.01f * y3;
    float v0 = g_xs[idx];
    float v1 = g_xs[(size_t)ND + idx];
    float v2 = g_xs[2 * (size_t)ND + idx];
    out[idx] = y3;
    out[(size_t)ND + idx] = 0.5f * (((v0 + v1) + v2) + y3);
    ((float4*)(out + 2 * (size_t)ND))[idx] = make_float4(v0, v1, v2, y3);
}

// ---------------- launch ----------------
extern "C" void kernel_launch(void* const* d_in, const int* in_sizes, int n_in,
                              void* d_out, int out_size) {
    const float* x    = (const float*)d_in[0];
    const int*   ei   = (const int*)  d_in[1];
    const float* bnw  = (const float*)d_in[2];
    const float* bnb  = (const float*)d_in[3];
    const float* bnm  = (const float*)d_in[4];
    const float* bnv  = (const float*)d_in[5];
    const float* W0   = (const float*)d_in[6];
    const float* Ws   = (const float*)d_in[7];
    const float* asrc = (const float*)d_in[8];
    const float* adst = (const float*)d_in[9];
    const float* bias = (const float*)d_in[10];
    const float* gnw  = (const float*)d_in[11];
    const float* gnb  = (const float*)d_in[12];
    const float* gns  = (const float*)d_in[13];
    float* out = (float*)d_out;

    static float* w0p_addr = nullptr;
    static cudaStream_t s2 = nullptr;
    static cudaEvent_t evA = nullptr, evB = nullptr;
    if (!w0p_addr) {
        cudaGetSymbolAddress((void**)&w0p_addr, g_W0p);
        cudaStreamCreateWithFlags(&s2, cudaStreamNonBlocking);
        cudaEventCreateWithFlags(&evA, cudaEventDisableTiming);
        cudaEventCreateWithFlags(&evB, cudaEventDisableTiming);
    }

    // prep on default stream; fork CSR build onto s2; GEMM0 runs concurrently.
    k_prepzero<<<(N_NODES + 255) / 256, 256>>>(W0, bnw, bnb, bnm, bnv);
    cudaEventRecord(evA, 0);
    cudaStreamWaitEvent(s2, evA, 0);
    k_count<<<(N_EDGES / 4 + 255) / 256, 256, 0, s2>>>(ei);
    k_bsum<<<SCAN_B, 256, 0, s2>>>();
    k_gemm<<<(N_NODES + 63) / 64, 256>>>(x, w0p_addr, F_IN, asrc, adst, 0,
                                         gnw, gnb, gns);
    k_bscan<<<1, 64, 0, s2>>>();
    k_offs<<<SCAN_B, 256, 0, s2>>>();
    k_scatter<<<(N_EDGES / 4 + 255) / 256, 256, 0, s2>>>(ei);
    cudaEventRecord(evB, s2);
    cudaStreamWaitEvent(0, evB, 0);   // join before agg needs the CSR

    for (int l = 0; l < L; ++l) {
        if (l > 0) {
            const float* W = Ws + (size_t)(l - 1) * D * D;
            k_gemm<<<(N_NODES + 63) / 64, 256>>>(
                nullptr, W, D, asrc + l * D, adst + l * D, l,
                gnw + (l - 1) * D, gnb + (l - 1) * D, gns + (l - 1) * D);
        }
        k_agg<<<N_NODES / 8, 256>>>(bias + l * D, l);
    }
    k_epilogue<<<(ND + 255) / 256, 256>>>(out, gnw + 3 * D, gnb + 3 * D, gns + 3 * D);
}